// round 4
// baseline (speedup 1.0000x reference)
#include <cuda_runtime.h>
#include <cuda_bf16.h>
#include <cstdint>

#define BATCH   65536
#define DIM     128
#define NPROTO  512
#define ODIM    8
#define MTILE   128
#define NCHUNK  64
#define NCHUNKS 8
#define NTHREADS 512

#define ASTRIDE 272                    // bytes per smem row (conflict-free ldmatrix)
#define ASPLIT  (MTILE * ASTRIDE)      // 34816 per split matrix
#define MATB    (NCHUNK * ASTRIDE)     // 17408 per B split matrix
#define BBUF    (3 * MATB)             // 52224 per B buffer

#define SM_BIAS 0
#define SM_A    2048
#define SM_B    (SM_A + 3 * ASPLIT)    // 106496
#define SM_RED  SM_A
#define SMEM_TOTAL (SM_B + 2 * BBUF)   // 210944

__device__ __align__(16) __nv_bfloat16 g_w[3][NPROTO * DIM];  // h/m/l of r^2*proto, [p][d]
__device__ float g_bias[NPROTO];

// ---------------- helpers ----------------
__device__ __forceinline__ uint32_t smem_u32(const void* p) {
    uint32_t a;
    asm("{ .reg .u64 t; cvta.to.shared.u64 t, %1; cvt.u32.u64 %0, t; }" : "=r"(a) : "l"(p));
    return a;
}
__device__ __forceinline__ void ldsm4(uint32_t* r, uint32_t a) {
    asm volatile("ldmatrix.sync.aligned.m8n8.x4.shared.b16 {%0,%1,%2,%3}, [%4];"
                 : "=r"(r[0]), "=r"(r[1]), "=r"(r[2]), "=r"(r[3]) : "r"(a));
}
__device__ __forceinline__ void mma16816(float* d, const uint32_t* a, const uint32_t* b) {
    asm volatile(
        "mma.sync.aligned.m16n8k16.row.col.f32.bf16.bf16.f32 "
        "{%0,%1,%2,%3}, {%4,%5,%6,%7}, {%8,%9}, {%0,%1,%2,%3};"
        : "+f"(d[0]), "+f"(d[1]), "+f"(d[2]), "+f"(d[3])
        : "r"(a[0]), "r"(a[1]), "r"(a[2]), "r"(a[3]), "r"(b[0]), "r"(b[1]));
}
__device__ __forceinline__ void cp_async16(uint32_t dst, const void* src) {
    asm volatile("cp.async.cg.shared.global [%0], [%1], 16;" :: "r"(dst), "l"(src));
}

// ---------------------------------------------------------------------------
// Prep: split w = r^2 * proto into bf16 h/m/l, compute bias.
// ---------------------------------------------------------------------------
__global__ void prep_kernel(const float* __restrict__ protos,
                            const float* __restrict__ relevance) {
    int p = blockIdx.x;          // 512
    int d = threadIdx.x;         // 128
    float r  = relevance[d];
    float pv = protos[p * DIM + d];
    float w  = r * r * pv;

    __nv_bfloat16 h = __float2bfloat16_rn(w);
    float r1 = w - __bfloat162float(h);
    __nv_bfloat16 m = __float2bfloat16_rn(r1);
    float r2v = r1 - __bfloat162float(m);
    __nv_bfloat16 l = __float2bfloat16_rn(r2v);
    g_w[0][p * DIM + d] = h;
    g_w[1][p * DIM + d] = m;
    g_w[2][p * DIM + d] = l;

    float part = w * pv;
    __shared__ float red[4];
    #pragma unroll
    for (int off = 16; off > 0; off >>= 1)
        part += __shfl_down_sync(0xffffffffu, part, off);
    if ((d & 31) == 0) red[d >> 5] = part;
    __syncthreads();
    if (d == 0) g_bias[p] = -0.5f * (red[0] + red[1] + red[2] + red[3]);
}

// ---------------------------------------------------------------------------
// Main kernel: 512 threads (16 warps, 4/SMSP), warp tile 32x16.
// ---------------------------------------------------------------------------
extern __shared__ char smem[];

__global__ void __launch_bounds__(NTHREADS, 1)
grlvq_main(const float* __restrict__ x,
           const float* __restrict__ proto_out,
           float* __restrict__ out) {
    const uint32_t sb = smem_u32(smem);
    const int tid  = threadIdx.x;
    const int wid  = tid >> 5;
    const int lane = tid & 31;
    const int row0 = blockIdx.x * MTILE;
    const int wm = (wid & 3) * 32;     // warp M offset (4 M-warps)
    const int wn = (wid >> 2) * 16;    // warp N offset within chunk (4 N-warps)

    // bias -> smem
    for (int i = tid; i < NPROTO; i += NTHREADS)
        ((float*)(smem + SM_BIAS))[i] = g_bias[i];

    // ---- issue B chunks via cp.async ----
    #define ISSUE_B(c, buf)                                                        \
        do {                                                                       \
            for (int i = tid; i < 3072; i += NTHREADS) {                           \
                int mat = i >> 10, rem = i & 1023, rr = rem >> 4, q = rem & 15;    \
                const void* src = &g_w[mat][(size_t)((c) * NCHUNK + rr) * DIM + q * 8]; \
                uint32_t dst = sb + SM_B + (buf) * BBUF + mat * MATB               \
                             + rr * ASTRIDE + q * 16;                              \
                cp_async16(dst, src);                                              \
            }                                                                      \
            asm volatile("cp.async.commit_group;" ::: "memory");                   \
        } while (0)

    ISSUE_B(0, 0);
    ISSUE_B(1, 1);

    // ---- A: load x tile, split into h/m/l bf16, store padded layout ----
    {
        const int r  = tid >> 2;               // 128 rows
        const int cb = (tid & 3) * 32;         // 4 col-blocks of 32
        const float4* xr = (const float4*)(x + (size_t)(row0 + r) * DIM + cb);
        #pragma unroll
        for (int g = 0; g < 4; g++) {          // 4 groups of 8 columns
            float4 v0 = xr[g * 2], v1 = xr[g * 2 + 1];
            float xv[8] = {v0.x, v0.y, v0.z, v0.w, v1.x, v1.y, v1.z, v1.w};
            uint32_t hh[4], mm[4], ll[4];
            #pragma unroll
            for (int q = 0; q < 4; q++) {
                float a0 = xv[2 * q], a1 = xv[2 * q + 1];
                __nv_bfloat16 h0 = __float2bfloat16_rn(a0), h1 = __float2bfloat16_rn(a1);
                float r0 = a0 - __bfloat162float(h0), r1f = a1 - __bfloat162float(h1);
                __nv_bfloat16 m0 = __float2bfloat16_rn(r0), m1 = __float2bfloat16_rn(r1f);
                float s0 = r0 - __bfloat162float(m0), s1 = r1f - __bfloat162float(m1);
                __nv_bfloat16 l0 = __float2bfloat16_rn(s0), l1 = __float2bfloat16_rn(s1);
                hh[q] = ((uint32_t)__bfloat16_as_ushort(h1) << 16) | __bfloat16_as_ushort(h0);
                mm[q] = ((uint32_t)__bfloat16_as_ushort(m1) << 16) | __bfloat16_as_ushort(m0);
                ll[q] = ((uint32_t)__bfloat16_as_ushort(l1) << 16) | __bfloat16_as_ushort(l0);
            }
            uint32_t off = (uint32_t)r * ASTRIDE + (uint32_t)(cb + g * 8) * 2;
            *(uint4*)(smem + SM_A + 0 * ASPLIT + off) = make_uint4(hh[0], hh[1], hh[2], hh[3]);
            *(uint4*)(smem + SM_A + 1 * ASPLIT + off) = make_uint4(mm[0], mm[1], mm[2], mm[3]);
            *(uint4*)(smem + SM_A + 2 * ASPLIT + off) = make_uint4(ll[0], ll[1], ll[2], ll[3]);
        }
    }

    // Per-thread running argmax: 4 local row slots (mt*2 + half).
    float bestv[4];
    int   besti[4];
    #pragma unroll
    for (int i = 0; i < 4; i++) { bestv[i] = -3.402823466e38f; besti[i] = 0; }

    // ldmatrix base addressing
    const uint32_t a_row = (uint32_t)(wm + (lane & 15));
    const uint32_t a_kh  = (uint32_t)(lane >> 4) * 16;
    const uint32_t b_row = (uint32_t)(wn + ((lane >> 4) & 1) * 8 + (lane & 7));
    const uint32_t b_kh  = (uint32_t)((lane >> 3) & 1) * 16;

    static const int TA[6] = {0, 0, 1, 1, 0, 2};
    static const int TB[6] = {0, 1, 0, 1, 2, 0};

    for (int c = 0; c < NCHUNKS; c++) {
        asm volatile("cp.async.wait_group 1;" ::: "memory");
        __syncthreads();
        const uint32_t bbase = sb + SM_B + (c & 1) * BBUF;

        float acc[2][2][4];
        #pragma unroll
        for (int mt = 0; mt < 2; mt++)
            #pragma unroll
            for (int nt = 0; nt < 2; nt++)
                #pragma unroll
                for (int j = 0; j < 4; j++) acc[mt][nt][j] = 0.0f;

        #pragma unroll
        for (int kk = 0; kk < 8; kk++) {
            uint32_t af[3][2][4];
            #pragma unroll
            for (int s = 0; s < 3; s++)
                #pragma unroll
                for (int mt = 0; mt < 2; mt++)
                    ldsm4(af[s][mt],
                          sb + SM_A + s * ASPLIT + (a_row + mt * 16) * ASTRIDE
                          + kk * 32 + a_kh);
            uint32_t bf[3][4];
            #pragma unroll
            for (int s = 0; s < 3; s++)
                ldsm4(bf[s], bbase + s * MATB + b_row * ASTRIDE + kk * 32 + b_kh);
            #pragma unroll
            for (int t = 0; t < 6; t++) {
                #pragma unroll
                for (int mt = 0; mt < 2; mt++)
                    #pragma unroll
                    for (int nt = 0; nt < 2; nt++)
                        mma16816(acc[mt][nt], af[TA[t]][mt], &bf[TB[t]][nt * 2]);
            }
        }

        // epilogue: bias + running argmax
        const float* bias_s = (const float*)(smem + SM_BIAS);
        #pragma unroll
        for (int mt = 0; mt < 2; mt++) {
            #pragma unroll
            for (int nt = 0; nt < 2; nt++) {
                const int col = c * NCHUNK + wn + nt * 8 + (lane & 3) * 2;
                float b0 = bias_s[col], b1 = bias_s[col + 1];
                float v0 = acc[mt][nt][0] + b0;   // row r
                float v1 = acc[mt][nt][1] + b1;
                float v2 = acc[mt][nt][2] + b0;   // row r+8
                float v3 = acc[mt][nt][3] + b1;
                int s0 = mt * 2, s1 = mt * 2 + 1;
                if (v0 > bestv[s0]) { bestv[s0] = v0; besti[s0] = col; }
                if (v1 > bestv[s0]) { bestv[s0] = v1; besti[s0] = col + 1; }
                if (v2 > bestv[s1]) { bestv[s1] = v2; besti[s1] = col; }
                if (v3 > bestv[s1]) { bestv[s1] = v3; besti[s1] = col + 1; }
            }
        }

        __syncthreads();
        if (c + 2 < NCHUNKS) ISSUE_B(c + 2, c & 1);
    }

    // ---- cross-thread reduction: 16 candidates per row ----
    float* redv = (float*)(smem + SM_RED);
    int*   redi = (int*)(smem + SM_RED + 8192);
    const int slot = ((wid >> 2) << 2) | (lane & 3);   // 0..15
    #pragma unroll
    for (int sl = 0; sl < 4; sl++) {
        int mt = sl >> 1, half = sl & 1;
        int row = wm + mt * 16 + half * 8 + (lane >> 2);
        redv[row * 16 + slot] = bestv[sl];
        redi[row * 16 + slot] = besti[sl];
    }
    __syncthreads();

    if (tid < MTILE) {
        float bv = redv[tid * 16];
        int   bi = redi[tid * 16];
        #pragma unroll
        for (int j = 1; j < 16; j++) {
            float v  = redv[tid * 16 + j];
            int   ix = redi[tid * 16 + j];
            if (v > bv || (v == bv && ix < bi)) { bv = v; bi = ix; }
        }
        const float4* po = (const float4*)proto_out;
        float4* o = (float4*)(out + (size_t)(row0 + tid) * ODIM);
        o[0] = po[bi * 2];
        o[1] = po[bi * 2 + 1];
    }
}

// ---------------------------------------------------------------------------
extern "C" void kernel_launch(void* const* d_in, const int* in_sizes, int n_in,
                              void* d_out, int out_size) {
    const float* x         = (const float*)d_in[0];  // [65536,128]
    const float* protos    = (const float*)d_in[1];  // [512,128]
    const float* proto_out = (const float*)d_in[2];  // [512,8]
    const float* relevance = (const float*)d_in[3];  // [128]
    float* out = (float*)d_out;                      // [65536,8]

    prep_kernel<<<NPROTO, DIM>>>(protos, relevance);

    cudaFuncSetAttribute(grlvq_main,
                         cudaFuncAttributeMaxDynamicSharedMemorySize, SMEM_TOTAL);
    grlvq_main<<<BATCH / MTILE, NTHREADS, SMEM_TOTAL>>>(x, proto_out, out);
}

// round 5
// speedup vs baseline: 1.7399x; 1.7399x over previous
#include <cuda_runtime.h>
#include <cuda_fp16.h>
#include <cstdint>

#define BATCH   65536
#define DIM     128
#define NPROTO  512
#define ODIM    8
#define MTILE   128
#define NCHUNK  32
#define NCHUNKS 16
#define NTHREADS 256

#define ASTRIDE 272                    // bytes per smem row (conflict-free ldmatrix)
#define ASPLIT  (MTILE * ASTRIDE)      // 34816 per split matrix
#define MATB    (NCHUNK * ASTRIDE)     // 8704 per B split matrix
#define BBUF    (2 * MATB)             // 17408 per B buffer (2 splits)

#define SM_BIAS 0
#define SM_A    2048
#define SM_B    (SM_A + 2 * ASPLIT)    // 71680
#define SM_RED  SM_A
#define SMEM_TOTAL (SM_B + 2 * BBUF)   // 106496  (2 CTAs/SM: 208KB < 227KB)

__device__ __align__(16) __half g_w[2][NPROTO * DIM];  // h/m fp16 split of r^2*proto, [p][d]
__device__ float g_bias[NPROTO];

// ---------------- helpers ----------------
__device__ __forceinline__ uint32_t smem_u32(const void* p) {
    uint32_t a;
    asm("{ .reg .u64 t; cvta.to.shared.u64 t, %1; cvt.u32.u64 %0, t; }" : "=r"(a) : "l"(p));
    return a;
}
__device__ __forceinline__ void ldsm4(uint32_t* r, uint32_t a) {
    asm volatile("ldmatrix.sync.aligned.m8n8.x4.shared.b16 {%0,%1,%2,%3}, [%4];"
                 : "=r"(r[0]), "=r"(r[1]), "=r"(r[2]), "=r"(r[3]) : "r"(a));
}
__device__ __forceinline__ void mma16816(float* d, const uint32_t* a, const uint32_t* b) {
    asm volatile(
        "mma.sync.aligned.m16n8k16.row.col.f32.f16.f16.f32 "
        "{%0,%1,%2,%3}, {%4,%5,%6,%7}, {%8,%9}, {%0,%1,%2,%3};"
        : "+f"(d[0]), "+f"(d[1]), "+f"(d[2]), "+f"(d[3])
        : "r"(a[0]), "r"(a[1]), "r"(a[2]), "r"(a[3]), "r"(b[0]), "r"(b[1]));
}
__device__ __forceinline__ void cp_async16(uint32_t dst, const void* src) {
    asm volatile("cp.async.cg.shared.global [%0], [%1], 16;" :: "r"(dst), "l"(src));
}

// ---------------------------------------------------------------------------
// Prep: split w = r^2 * proto into fp16 h/m, compute bias.
// ---------------------------------------------------------------------------
__global__ void prep_kernel(const float* __restrict__ protos,
                            const float* __restrict__ relevance) {
    int p = blockIdx.x;          // 512
    int d = threadIdx.x;         // 128
    float r  = relevance[d];
    float pv = protos[p * DIM + d];
    float w  = r * r * pv;

    __half h = __float2half_rn(w);
    __half m = __float2half_rn(w - __half2float(h));
    g_w[0][p * DIM + d] = h;
    g_w[1][p * DIM + d] = m;

    float part = w * pv;
    __shared__ float red[4];
    #pragma unroll
    for (int off = 16; off > 0; off >>= 1)
        part += __shfl_down_sync(0xffffffffu, part, off);
    if ((d & 31) == 0) red[d >> 5] = part;
    __syncthreads();
    if (d == 0) g_bias[p] = -0.5f * (red[0] + red[1] + red[2] + red[3]);
}

// ---------------------------------------------------------------------------
// Main kernel: 256 threads, 2 CTAs/SM, fp16 2-split x 3 terms.
// Warp layout: 4 M-warps x 2 N-warps; warp tile 32x16; chunk N=32.
// ---------------------------------------------------------------------------
extern __shared__ char smem[];

__global__ void __launch_bounds__(NTHREADS, 2)
grlvq_main(const float* __restrict__ x,
           const float* __restrict__ proto_out,
           float* __restrict__ out) {
    const uint32_t sb = smem_u32(smem);
    const int tid  = threadIdx.x;
    const int wid  = tid >> 5;
    const int lane = tid & 31;
    const int row0 = blockIdx.x * MTILE;
    const int wm = (wid & 3) * 32;     // warp M offset (4 M-warps)
    const int wn = (wid >> 2) * 16;    // warp N offset within chunk (2 N-warps)

    // bias -> smem
    for (int i = tid; i < NPROTO; i += NTHREADS)
        ((float*)(smem + SM_BIAS))[i] = g_bias[i];

    // ---- issue B chunks via cp.async: 2 mats x 32 rows x 16 uint4 = 1024 ----
    #define ISSUE_B(c, buf)                                                        \
        do {                                                                       \
            for (int i = tid; i < 1024; i += NTHREADS) {                           \
                int mat = i >> 9, rem = i & 511, rr = rem >> 4, q = rem & 15;      \
                const void* src = &g_w[mat][(size_t)((c) * NCHUNK + rr) * DIM + q * 8]; \
                uint32_t dst = sb + SM_B + (buf) * BBUF + mat * MATB               \
                             + rr * ASTRIDE + q * 16;                              \
                cp_async16(dst, src);                                              \
            }                                                                      \
            asm volatile("cp.async.commit_group;" ::: "memory");                   \
        } while (0)

    ISSUE_B(0, 0);
    ISSUE_B(1, 1);

    // ---- A: load x tile, split into fp16 h/m, store padded layout ----
    {
        const int r  = tid >> 1;
        const int cb = (tid & 1) * 64;
        const float4* xr = (const float4*)(x + (size_t)(row0 + r) * DIM + cb);
        #pragma unroll
        for (int g = 0; g < 8; g++) {
            float4 v0 = xr[g * 2], v1 = xr[g * 2 + 1];
            float xv[8] = {v0.x, v0.y, v0.z, v0.w, v1.x, v1.y, v1.z, v1.w};
            uint32_t hh[4], mm[4];
            #pragma unroll
            for (int q = 0; q < 4; q++) {
                float a0 = xv[2 * q], a1 = xv[2 * q + 1];
                __half h0 = __float2half_rn(a0), h1 = __float2half_rn(a1);
                float r0 = a0 - __half2float(h0), r1f = a1 - __half2float(h1);
                __half m0 = __float2half_rn(r0), m1 = __float2half_rn(r1f);
                hh[q] = ((uint32_t)__half_as_ushort(h1) << 16) | __half_as_ushort(h0);
                mm[q] = ((uint32_t)__half_as_ushort(m1) << 16) | __half_as_ushort(m0);
            }
            uint32_t off = (uint32_t)r * ASTRIDE + (uint32_t)(cb + g * 8) * 2;
            *(uint4*)(smem + SM_A + 0 * ASPLIT + off) = make_uint4(hh[0], hh[1], hh[2], hh[3]);
            *(uint4*)(smem + SM_A + 1 * ASPLIT + off) = make_uint4(mm[0], mm[1], mm[2], mm[3]);
        }
    }

    // Per-thread running argmax: 4 local row slots (mt*2 + half).
    float bestv[4];
    int   besti[4];
    #pragma unroll
    for (int i = 0; i < 4; i++) { bestv[i] = -3.402823466e38f; besti[i] = 0; }

    // ldmatrix base addressing
    const uint32_t a_row = (uint32_t)(wm + (lane & 15));
    const uint32_t a_kh  = (uint32_t)(lane >> 4) * 16;
    const uint32_t b_row = (uint32_t)(wn + ((lane >> 4) & 1) * 8 + (lane & 7));
    const uint32_t b_kh  = (uint32_t)((lane >> 3) & 1) * 16;

    // 3 terms: hh, hM, mH
    static const int TA[3] = {0, 0, 1};
    static const int TB[3] = {0, 1, 0};

    for (int c = 0; c < NCHUNKS; c++) {
        asm volatile("cp.async.wait_group 1;" ::: "memory");
        __syncthreads();
        const uint32_t bbase = sb + SM_B + (c & 1) * BBUF;

        float acc[2][2][4];
        #pragma unroll
        for (int mt = 0; mt < 2; mt++)
            #pragma unroll
            for (int nt = 0; nt < 2; nt++)
                #pragma unroll
                for (int j = 0; j < 4; j++) acc[mt][nt][j] = 0.0f;

        #pragma unroll
        for (int kk = 0; kk < 8; kk++) {
            uint32_t af[2][2][4];
            #pragma unroll
            for (int s = 0; s < 2; s++)
                #pragma unroll
                for (int mt = 0; mt < 2; mt++)
                    ldsm4(af[s][mt],
                          sb + SM_A + s * ASPLIT + (a_row + mt * 16) * ASTRIDE
                          + kk * 32 + a_kh);
            uint32_t bf[2][4];
            #pragma unroll
            for (int s = 0; s < 2; s++)
                ldsm4(bf[s], bbase + s * MATB + b_row * ASTRIDE + kk * 32 + b_kh);
            #pragma unroll
            for (int t = 0; t < 3; t++) {
                #pragma unroll
                for (int mt = 0; mt < 2; mt++)
                    #pragma unroll
                    for (int nt = 0; nt < 2; nt++)
                        mma16816(acc[mt][nt], af[TA[t]][mt], &bf[TB[t]][nt * 2]);
            }
        }

        // epilogue: bias + running argmax
        const float* bias_s = (const float*)(smem + SM_BIAS);
        #pragma unroll
        for (int mt = 0; mt < 2; mt++) {
            #pragma unroll
            for (int nt = 0; nt < 2; nt++) {
                const int col = c * NCHUNK + wn + nt * 8 + (lane & 3) * 2;
                float b0 = bias_s[col], b1 = bias_s[col + 1];
                float v0 = acc[mt][nt][0] + b0;   // row r
                float v1 = acc[mt][nt][1] + b1;
                float v2 = acc[mt][nt][2] + b0;   // row r+8
                float v3 = acc[mt][nt][3] + b1;
                int s0 = mt * 2, s1 = mt * 2 + 1;
                if (v0 > bestv[s0]) { bestv[s0] = v0; besti[s0] = col; }
                if (v1 > bestv[s0]) { bestv[s0] = v1; besti[s0] = col + 1; }
                if (v2 > bestv[s1]) { bestv[s1] = v2; besti[s1] = col; }
                if (v3 > bestv[s1]) { bestv[s1] = v3; besti[s1] = col + 1; }
            }
        }

        __syncthreads();
        if (c + 2 < NCHUNKS) ISSUE_B(c + 2, c & 1);
    }

    // ---- cross-thread reduction: 8 candidates per row ----
    float* redv = (float*)(smem + SM_RED);
    int*   redi = (int*)(smem + SM_RED + 4096);
    const int slot = ((wid >> 2) << 2) | (lane & 3);   // 0..7
    #pragma unroll
    for (int sl = 0; sl < 4; sl++) {
        int mt = sl >> 1, half = sl & 1;
        int row = wm + mt * 16 + half * 8 + (lane >> 2);
        redv[row * 8 + slot] = bestv[sl];
        redi[row * 8 + slot] = besti[sl];
    }
    __syncthreads();

    if (tid < MTILE) {
        float bv = redv[tid * 8];
        int   bi = redi[tid * 8];
        #pragma unroll
        for (int j = 1; j < 8; j++) {
            float v  = redv[tid * 8 + j];
            int   ix = redi[tid * 8 + j];
            if (v > bv || (v == bv && ix < bi)) { bv = v; bi = ix; }
        }
        const float4* po = (const float4*)proto_out;
        float4* o = (float4*)(out + (size_t)(row0 + tid) * ODIM);
        o[0] = po[bi * 2];
        o[1] = po[bi * 2 + 1];
    }
}

// ---------------------------------------------------------------------------
extern "C" void kernel_launch(void* const* d_in, const int* in_sizes, int n_in,
                              void* d_out, int out_size) {
    const float* x         = (const float*)d_in[0];  // [65536,128]
    const float* protos    = (const float*)d_in[1];  // [512,128]
    const float* proto_out = (const float*)d_in[2];  // [512,8]
    const float* relevance = (const float*)d_in[3];  // [128]
    float* out = (float*)d_out;                      // [65536,8]

    prep_kernel<<<NPROTO, DIM>>>(protos, relevance);

    cudaFuncSetAttribute(grlvq_main,
                         cudaFuncAttributeMaxDynamicSharedMemorySize, SMEM_TOTAL);
    grlvq_main<<<BATCH / MTILE, NTHREADS, SMEM_TOTAL>>>(x, proto_out, out);
}